// round 3
// baseline (speedup 1.0000x reference)
#include <cuda_runtime.h>
#include <math.h>

// Problem constants (fixed by setup_inputs)
#define N_NODES 4096
#define IN_DIM  512
#define H_DIM   256
#define OUTD    64
#define MAXDEG  192          // mean deg ~64, sigma ~8; huge headroom
#define EPSV    1e-8f
#define A_SCAD  3.7f
#define PROP_STEP 4
#define NB1     32769        // level-1 bins: key = float_bits >> 15, y in [0,2] -> key <= 32768
#define NB2     32768        // level-2 bins: low 15 bits

static const float LAMF = (float)(1.0 / 0.9 - 1.0);   // 1/LAM_HAT - 1

// ---------------- device scratch (static, no allocation) ----------------
__device__ float g_dsq[N_NODES];
__device__ int   g_cnt[N_NODES];
__device__ int   g_cols[N_NODES * MAXDEG];
__device__ float g_y   [N_NODES * MAXDEG];
__device__ float g_Fu  [N_NODES * OUTD];
__device__ float g_F0  [N_NODES * OUTD];
__device__ float g_FA  [N_NODES * OUTD];
__device__ float g_FB  [N_NODES * OUTD];
__device__ float g_H   [N_NODES * H_DIM];
__device__ unsigned g_hist1[NB1];
__device__ unsigned g_histT[2 * NB2];
__device__ unsigned g_key[2];
__device__ int      g_rank[2];
__device__ float    g_frac;
__device__ float    g_lamc;
__device__ int      g_M;

// ---------------- reset: zero counters + histograms ----------------
__global__ void reset_kernel() {
    int i = blockIdx.x * blockDim.x + threadIdx.x;
    if (i == 0) g_M = 0;
    if (i < NB1) g_hist1[i] = 0;
    if (i < 2 * NB2) g_histT[i] = 0;
}

// ---------------- build padded adjacency (deterministic, column-sorted) ----
__global__ __launch_bounds__(256) void build_kernel(const float* __restrict__ A) {
    __shared__ unsigned char sbit[N_NODES];
    __shared__ int scnt[256];
    int row = blockIdx.x, tid = threadIdx.x;
    const float* Arow = A + (size_t)row * N_NODES;
    for (int i = tid; i < N_NODES; i += 256) sbit[i] = (Arow[i] != 0.0f);
    __syncthreads();
    int c0 = tid * 16;
    int cnt = 0;
#pragma unroll
    for (int c = 0; c < 16; c++) cnt += sbit[c0 + c];
    scnt[tid] = cnt;
    __syncthreads();
    for (int off = 1; off < 256; off <<= 1) {
        int v = (tid >= off) ? scnt[tid - off] : 0;
        __syncthreads();
        scnt[tid] += v;
        __syncthreads();
    }
    int base  = scnt[tid] - cnt;
    int total = scnt[255];
    int pos = base;
    for (int c = 0; c < 16; c++)
        if (sbit[c0 + c] && pos < MAXDEG) g_cols[row * MAXDEG + (pos++)] = c0 + c;
    if (tid == 0) {
        int t = min(total, MAXDEG);
        g_cnt[row] = t;
        g_dsq[row] = sqrtf((float)(total + 1));   // D = deg + self-loop
        atomicAdd(&g_M, t);
    }
}

// ---------------- software-pipelined fp32 GEMM: C = act(A @ B + bias) -------
template <bool RELU>
__global__ __launch_bounds__(256) void gemm64(const float* __restrict__ A,
                                              const float* __restrict__ B,
                                              const float* __restrict__ bias,
                                              float* __restrict__ C,
                                              int M, int N, int K) {
    __shared__ float As[16][64];   // [k][m]
    __shared__ float Bs[16][64];   // [k][n]
    int tid = threadIdx.x;
    int tx = tid & 15, ty = tid >> 4;
    int row0 = blockIdx.y * 64, col0 = blockIdx.x * 64;
    int ar = tid >> 2, ak = (tid & 3) * 4;      // A tile: 64 rows x 16 k
    int bk = tid >> 4, bc = (tid & 15) * 4;     // B tile: 16 k x 64 cols
    const float* Aptr = A + (size_t)(row0 + ar) * K + ak;
    const float* Bptr = B + (size_t)bk * N + col0 + bc;

    float acc[4][4];
#pragma unroll
    for (int i = 0; i < 4; i++)
#pragma unroll
        for (int j = 0; j < 4; j++) acc[i][j] = 0.0f;

    float4 av = *(const float4*)Aptr;
    float4 bv = *(const float4*)Bptr;

    for (int k0 = 0; k0 < K; k0 += 16) {
        As[ak + 0][ar] = av.x; As[ak + 1][ar] = av.y;
        As[ak + 2][ar] = av.z; As[ak + 3][ar] = av.w;
        *(float4*)&Bs[bk][bc] = bv;
        __syncthreads();
        if (k0 + 16 < K) {     // prefetch next tile: overlaps with the compute below
            av = *(const float4*)(Aptr + k0 + 16);
            bv = *(const float4*)(Bptr + (size_t)(k0 + 16) * N);
        }
#pragma unroll
        for (int kk = 0; kk < 16; kk++) {
            float4 a = *(float4*)&As[kk][ty * 4];
            float4 b = *(float4*)&Bs[kk][tx * 4];
            float avr[4] = {a.x, a.y, a.z, a.w};
            float bvr[4] = {b.x, b.y, b.z, b.w};
#pragma unroll
            for (int i = 0; i < 4; i++)
#pragma unroll
                for (int j = 0; j < 4; j++) acc[i][j] = fmaf(avr[i], bvr[j], acc[i][j]);
        }
        __syncthreads();
    }
#pragma unroll
    for (int i = 0; i < 4; i++) {
        int r = row0 + ty * 4 + i;
        float4 o;
        o.x = acc[i][0] + bias[col0 + tx * 4 + 0];
        o.y = acc[i][1] + bias[col0 + tx * 4 + 1];
        o.z = acc[i][2] + bias[col0 + tx * 4 + 2];
        o.w = acc[i][3] + bias[col0 + tx * 4 + 3];
        if (RELU) {
            o.x = fmaxf(o.x, 0.0f); o.y = fmaxf(o.y, 0.0f);
            o.z = fmaxf(o.z, 0.0f); o.w = fmaxf(o.w, 0.0f);
        }
        *(float4*)&C[(size_t)r * N + col0 + tx * 4] = o;
    }
}

// ---------------- Fu for iteration 0 (warp per row) --------------------------
__global__ __launch_bounds__(256) void normalize0_kernel(const float* __restrict__ F) {
    int w = (blockIdx.x * blockDim.x + threadIdx.x) >> 5;
    int lane = threadIdx.x & 31;
    if (w >= N_NODES) return;
    float d = g_dsq[w];
    float a = F[w * OUTD + lane] / d;
    float b = F[w * OUTD + lane + 32] / d;
    float s = a * a + b * b;
#pragma unroll
    for (int o = 16; o; o >>= 1) s += __shfl_xor_sync(0xffffffffu, s, o);
    float inv = 1.0f / fmaxf(sqrtf(s), EPSV);
    g_Fu[w * OUTD + lane]      = a * inv;
    g_Fu[w * OUTD + lane + 32] = b * inv;
}

// ---------------- per-edge y = clip(1 - Fu_i.Fu_j) + level-1 histogram -------
__global__ __launch_bounds__(256) void ycompute_kernel() {
    __shared__ float fu[OUTD];
    int row = blockIdx.x, tid = threadIdx.x;
    int lane = tid & 31, warp = tid >> 5;
    if (tid < OUTD) fu[tid] = g_Fu[row * OUTD + tid];
    __syncthreads();
    int cnt = g_cnt[row];
    for (int s = warp; s < MAXDEG; s += 8) {
        if (s < cnt) {
            int j = g_cols[row * MAXDEG + s];
            float p = fu[lane] * g_Fu[j * OUTD + lane]
                    + fu[lane + 32] * g_Fu[j * OUTD + lane + 32];
#pragma unroll
            for (int o = 16; o; o >>= 1) p += __shfl_xor_sync(0xffffffffu, p, o);
            if (lane == 0) {
                float yv = fminf(fmaxf(1.0f - p, 0.0f), 2.0f);
                g_y[row * MAXDEG + s] = yv;
                atomicAdd(&g_hist1[__float_as_uint(yv) >> 15], 1u);
            }
        } else if (lane == 0) {
            g_y[row * MAXDEG + s] = __int_as_float(0x7f800000);  // +inf padding
        }
    }
}

// ---------------- fin1: locate level-1 bin of ranks k0, k0+1 ----------------
__global__ __launch_bounds__(1024) void fin1_kernel() {
    __shared__ unsigned ssum[1024];
    int tid = threadIdx.x;
    const int CH = 33;                       // 1024*33 >= NB1
    int base = tid * CH;
    int lim = min(CH, NB1 - base); if (lim < 0) lim = 0;
    unsigned s = 0;
    for (int i = 0; i < lim; i++) s += g_hist1[base + i];
    ssum[tid] = s;
    __syncthreads();
    for (int off = 1; off < 1024; off <<= 1) {
        unsigned v = (tid >= off) ? ssum[tid - off] : 0;
        __syncthreads();
        ssum[tid] += v;
        __syncthreads();
    }
    unsigned incl = ssum[tid], excl = incl - s;
    int M = g_M;
    if (M <= 0) { if (tid == 0) { g_key[0] = g_key[1] = 0xFFFFFFFFu; g_frac = 0.f; } return; }
    double idx = 0.75 * (double)(M - 1);
    long k0l = (long)floor(idx);
    if (tid == 0) g_frac = (float)(idx - (double)k0l);
    int RR[2];
    RR[0] = (int)k0l;
    long k1 = k0l + 1; if (k1 > (long)(M - 1)) k1 = M - 1;
    RR[1] = (int)k1;
    for (int t = 0; t < 2; t++) {
        int r = RR[t];
        if (r >= (int)excl && r < (int)incl) {
            unsigned cum = excl;
            for (int i = 0; i < lim; i++) {
                unsigned c = g_hist1[base + i];
                if (cum + c > (unsigned)r) { g_key[t] = (unsigned)(base + i); g_rank[t] = r - (int)cum; break; }
                cum += c;
            }
        }
    }
}

// ---------------- refine: histogram low 15 bits of candidates ----------------
__global__ __launch_bounds__(256) void refine_kernel() {
    unsigned k0 = g_key[0], k1 = g_key[1];
    const int T = N_NODES * MAXDEG;
    for (int s = blockIdx.x * 256 + threadIdx.x; s < T; s += gridDim.x * 256) {
        unsigned u = __float_as_uint(g_y[s]);
        unsigned key = u >> 15;
        if (key == k0) atomicAdd(&g_histT[u & 0x7FFFu], 1u);
        if (key == k1) atomicAdd(&g_histT[NB2 + (u & 0x7FFFu)], 1u);
    }
}

// ---------------- fin2: exact order statistics -> lamc -----------------------
__global__ __launch_bounds__(1024) void fin2_kernel(const float* __restrict__ lg0,
                                                    const float* __restrict__ rdec,
                                                    const float* __restrict__ ralpha,
                                                    int kiter) {
    __shared__ unsigned ssum[1024];
    __shared__ float vres[2];
    int tid = threadIdx.x;
    for (int t = 0; t < 2; t++) {
        const unsigned* H = g_histT + t * NB2;
        int base = tid * 32;
        unsigned s = 0;
#pragma unroll 4
        for (int i = 0; i < 32; i++) s += H[base + i];
        __syncthreads();
        ssum[tid] = s;
        __syncthreads();
        for (int off = 1; off < 1024; off <<= 1) {
            unsigned v = (tid >= off) ? ssum[tid - off] : 0;
            __syncthreads();
            ssum[tid] += v;
            __syncthreads();
        }
        unsigned incl = ssum[tid], excl = incl - s;
        int r = g_rank[t];
        if (g_M > 0 && r >= (int)excl && r < (int)incl) {
            unsigned cum = excl;
            for (int i = 0; i < 32; i++) {
                unsigned c = H[base + i];
                if (cum + c > (unsigned)r) {
                    unsigned u = (g_key[t] << 15) | (unsigned)(base + i);
                    vres[t] = __uint_as_float(u);
                    break;
                }
                cum += c;
            }
        }
        __syncthreads();
    }
    if (tid == 0) {
        float gd;
        if (g_M > 0) {
            float fr = g_frac;
            gd = vres[0] * (1.0f - fr) + vres[1] * fr;   // linear interpolation
        } else {
            gd = 1.0f;
        }
        gd = fmaxf(gd, EPSV);
        float g0 = expf(lg0[0]);
        float rr = 1.0f / (1.0f + expf(-rdec[0]));
        float gp = g0 * powf(rr, (float)kiter);
        float al = 1.0f / (1.0f + expf(-ralpha[0]));
        g_lamc = al * (gp / A_SCAD) + (1.0f - al) * (gd / A_SCAD);
    }
}

// ------- SCAD weights + sparse propagation (+fused normalize, hist zeroing) --
__global__ __launch_bounds__(64) void propagate_kernel(const float* __restrict__ Fin,
                                                       float* __restrict__ Fout,
                                                       float lam, int write_fu) {
    __shared__ float ssc[MAXDEG];
    __shared__ int   sj[MAXDEG];
    __shared__ float red[2];
    int row = blockIdx.x, t = threadIdx.x;

    // zero the (now dead) histograms for the next iteration
    {
        int gid = row * 64 + t;
        if (gid < NB1) g_hist1[gid] = 0;
        else { int h = gid - NB1; if (h < 2 * NB2) g_histT[h] = 0; }
    }

    int cnt = g_cnt[row];
    float lamc = g_lamc;
    float di = g_dsq[row];
    float ps = 0.0f;
    for (int e = t; e < cnt; e += 64) {
        float y  = g_y[row * MAXDEG + e];
        float ys = fmaxf(y, EPSV);
        float wm = (A_SCAD * lamc - y) / ((A_SCAD - 1.0f) * ys);
        float w  = (y <= lamc) ? 1.0f : ((y <= A_SCAD * lamc) ? wm : 0.0f);
        int j = g_cols[row * MAXDEG + e];
        ssc[e] = w / (di * g_dsq[j]);        // W * A_tilde at the edge
        sj[e]  = j;
        ps += w;
    }
    // block reduce of ps (2 warps)
#pragma unroll
    for (int o = 16; o; o >>= 1) ps += __shfl_xor_sync(0xffffffffu, ps, o);
    if ((t & 31) == 0) red[t >> 5] = ps;
    __syncthreads();
    float S = red[0] + red[1];
    float Q = S / (float)(cnt + 1) + lam;    // D = cnt + 1 (self-loop)
    float acc = 0.0f;
    for (int e = 0; e < cnt; e++)
        acc = fmaf(ssc[e], Fin[sj[e] * OUTD + t], acc);
    float f0 = g_F0[row * OUTD + t];
    float outv = acc / Q + lam * f0 / Q;
    Fout[row * OUTD + t] = outv;

    if (write_fu) {                          // fused normalize for the NEXT iter
        float v = outv / di;
        float s2 = v * v;
#pragma unroll
        for (int o = 16; o; o >>= 1) s2 += __shfl_xor_sync(0xffffffffu, s2, o);
        __shared__ float red2[2];
        if ((t & 31) == 0) red2[t >> 5] = s2;
        __syncthreads();
        float nrm = sqrtf(red2[0] + red2[1]);
        g_Fu[row * OUTD + t] = v / fmaxf(nrm, EPSV);
    }
}

// ---------------- host launcher ---------------------------------------------
extern "C" void kernel_launch(void* const* d_in, const int* in_sizes, int n_in,
                              void* d_out, int out_size) {
    const float* A      = (const float*)d_in[0];
    const float* X      = (const float*)d_in[1];
    const float* W1     = (const float*)d_in[2];
    const float* b1     = (const float*)d_in[3];
    const float* W2     = (const float*)d_in[4];
    const float* b2     = (const float*)d_in[5];
    const float* lg0    = (const float*)d_in[6];
    const float* rdec   = (const float*)d_in[7];
    const float* ralpha = (const float*)d_in[8];
    float* out = (float*)d_out;

    float *pH, *pF0, *pFA, *pFB;
    cudaGetSymbolAddress((void**)&pH,  g_H);
    cudaGetSymbolAddress((void**)&pF0, g_F0);
    cudaGetSymbolAddress((void**)&pFA, g_FA);
    cudaGetSymbolAddress((void**)&pFB, g_FB);

    reset_kernel<<<(NB1 + 2 * NB2 + 255) / 256, 256>>>();
    build_kernel<<<N_NODES, 256>>>(A);

    // F0 = relu(X @ W1 + b1) @ W2 + b2
    gemm64<true ><<<dim3(H_DIM / 64, N_NODES / 64), 256>>>(X, W1, b1, pH,
                                                           N_NODES, H_DIM, IN_DIM);
    gemm64<false><<<dim3(OUTD / 64, N_NODES / 64), 256>>>(pH, W2, b2, pF0,
                                                          N_NODES, OUTD, H_DIM);
    normalize0_kernel<<<(N_NODES * 32 + 255) / 256, 256>>>(pF0);

    for (int k = 0; k < PROP_STEP; k++) {
        const float* Fin = (k == 0) ? pF0 : ((k & 1) ? pFA : pFB);
        float* Fout = (k == PROP_STEP - 1) ? out : ((k & 1) ? pFB : pFA);

        ycompute_kernel<<<N_NODES, 256>>>();
        fin1_kernel<<<1, 1024>>>();
        refine_kernel<<<256, 256>>>();
        fin2_kernel<<<1, 1024>>>(lg0, rdec, ralpha, k);
        propagate_kernel<<<N_NODES, 64>>>(Fin, Fout, LAMF, (k < PROP_STEP - 1) ? 1 : 0);
    }
}

// round 4
// speedup vs baseline: 1.3518x; 1.3518x over previous
#include <cuda_runtime.h>
#include <math.h>

// Problem constants (fixed by setup_inputs)
#define N_NODES 4096
#define IN_DIM  512
#define H_DIM   256
#define OUTD    64
#define MAXDEG  192          // mean deg ~64, sigma ~8; huge headroom
#define EPSV    1e-8f
#define A_SCAD  3.7f
#define PROP_STEP 4

static const float LAMF = (float)(1.0 / 0.9 - 1.0);   // 1/LAM_HAT - 1

// ---------------- device scratch (static, no allocation) ----------------
__device__ float g_dsq[N_NODES];
__device__ int   g_cnt[N_NODES];
__device__ int   g_cols[N_NODES * MAXDEG];
__device__ float g_y   [N_NODES * MAXDEG];
__device__ float g_Fu  [N_NODES * OUTD];
__device__ float g_F0  [N_NODES * OUTD];
__device__ float g_FA  [N_NODES * OUTD];
__device__ float g_FB  [N_NODES * OUTD];
__device__ float g_H   [N_NODES * H_DIM];
__device__ unsigned g_hist0[256];
__device__ unsigned g_hist [512];      // two 256-bin histograms (rank k, rank k+1)
__device__ unsigned g_prefix[2];
__device__ int      g_rank[2];
__device__ float    g_frac;
__device__ float    g_lamc;
__device__ int      g_M;
__device__ int      g_ticket;

// ---------------- reset ----------------
__global__ void reset_kernel() {
    int i = threadIdx.x;
    if (i == 0) { g_M = 0; g_ticket = 0; }
    if (i < 256) g_hist0[i] = 0;
    if (i < 512) g_hist[i] = 0;
}

// ---------------- build padded adjacency (deterministic, column-sorted) ----
__global__ __launch_bounds__(256) void build_kernel(const float* __restrict__ A) {
    __shared__ unsigned char sbit[N_NODES];
    __shared__ int scnt[256];
    int row = blockIdx.x, tid = threadIdx.x;
    const float* Arow = A + (size_t)row * N_NODES;
    for (int i = tid; i < N_NODES; i += 256) sbit[i] = (Arow[i] != 0.0f);
    __syncthreads();
    int c0 = tid * 16;
    int cnt = 0;
#pragma unroll
    for (int c = 0; c < 16; c++) cnt += sbit[c0 + c];
    scnt[tid] = cnt;
    __syncthreads();
    for (int off = 1; off < 256; off <<= 1) {
        int v = (tid >= off) ? scnt[tid - off] : 0;
        __syncthreads();
        scnt[tid] += v;
        __syncthreads();
    }
    int base  = scnt[tid] - cnt;
    int total = scnt[255];
    int pos = base;
    for (int c = 0; c < 16; c++)
        if (sbit[c0 + c] && pos < MAXDEG) g_cols[row * MAXDEG + (pos++)] = c0 + c;
    if (tid == 0) {
        int t = min(total, MAXDEG);
        g_cnt[row] = t;
        g_dsq[row] = sqrtf((float)(total + 1));   // D = deg + self-loop
        atomicAdd(&g_M, t);
    }
}

// ---------------- software-pipelined fp32 GEMM: C = act(A @ B + bias) -------
template <bool RELU>
__global__ __launch_bounds__(256) void gemm64(const float* __restrict__ A,
                                              const float* __restrict__ B,
                                              const float* __restrict__ bias,
                                              float* __restrict__ C,
                                              int M, int N, int K) {
    __shared__ float As[16][64];   // [k][m]
    __shared__ float Bs[16][64];   // [k][n]
    int tid = threadIdx.x;
    int tx = tid & 15, ty = tid >> 4;
    int row0 = blockIdx.y * 64, col0 = blockIdx.x * 64;
    int ar = tid >> 2, ak = (tid & 3) * 4;      // A tile: 64 rows x 16 k
    int bk = tid >> 4, bc = (tid & 15) * 4;     // B tile: 16 k x 64 cols
    const float* Aptr = A + (size_t)(row0 + ar) * K + ak;
    const float* Bptr = B + (size_t)bk * N + col0 + bc;

    float acc[4][4];
#pragma unroll
    for (int i = 0; i < 4; i++)
#pragma unroll
        for (int j = 0; j < 4; j++) acc[i][j] = 0.0f;

    float4 av = *(const float4*)Aptr;
    float4 bv = *(const float4*)Bptr;

    for (int k0 = 0; k0 < K; k0 += 16) {
        As[ak + 0][ar] = av.x; As[ak + 1][ar] = av.y;
        As[ak + 2][ar] = av.z; As[ak + 3][ar] = av.w;
        *(float4*)&Bs[bk][bc] = bv;
        __syncthreads();
        if (k0 + 16 < K) {     // prefetch next tile: overlaps with the compute below
            av = *(const float4*)(Aptr + k0 + 16);
            bv = *(const float4*)(Bptr + (size_t)(k0 + 16) * N);
        }
#pragma unroll
        for (int kk = 0; kk < 16; kk++) {
            float4 a = *(float4*)&As[kk][ty * 4];
            float4 b = *(float4*)&Bs[kk][tx * 4];
            float avr[4] = {a.x, a.y, a.z, a.w};
            float bvr[4] = {b.x, b.y, b.z, b.w};
#pragma unroll
            for (int i = 0; i < 4; i++)
#pragma unroll
                for (int j = 0; j < 4; j++) acc[i][j] = fmaf(avr[i], bvr[j], acc[i][j]);
        }
        __syncthreads();
    }
#pragma unroll
    for (int i = 0; i < 4; i++) {
        int r = row0 + ty * 4 + i;
        float4 o;
        o.x = acc[i][0] + bias[col0 + tx * 4 + 0];
        o.y = acc[i][1] + bias[col0 + tx * 4 + 1];
        o.z = acc[i][2] + bias[col0 + tx * 4 + 2];
        o.w = acc[i][3] + bias[col0 + tx * 4 + 3];
        if (RELU) {
            o.x = fmaxf(o.x, 0.0f); o.y = fmaxf(o.y, 0.0f);
            o.z = fmaxf(o.z, 0.0f); o.w = fmaxf(o.w, 0.0f);
        }
        *(float4*)&C[(size_t)r * N + col0 + tx * 4] = o;
    }
}

// ---------------- Fu for iteration 0 (warp per row) --------------------------
__global__ __launch_bounds__(256) void normalize0_kernel(const float* __restrict__ F) {
    int w = (blockIdx.x * blockDim.x + threadIdx.x) >> 5;
    int lane = threadIdx.x & 31;
    if (w >= N_NODES) return;
    float d = g_dsq[w];
    float a = F[w * OUTD + lane] / d;
    float b = F[w * OUTD + lane + 32] / d;
    float s = a * a + b * b;
#pragma unroll
    for (int o = 16; o; o >>= 1) s += __shfl_xor_sync(0xffffffffu, s, o);
    float inv = 1.0f / fmaxf(sqrtf(s), EPSV);
    g_Fu[w * OUTD + lane]      = a * inv;
    g_Fu[w * OUTD + lane + 32] = b * inv;
}

// -------- per-edge y = clip(1 - Fu_i.Fu_j) + SHARED-privatized top-byte hist --
__global__ __launch_bounds__(128) void ycompute_kernel() {
    __shared__ float fu[OUTD];
    __shared__ unsigned hist[256];
    int row = blockIdx.x, tid = threadIdx.x;
    int lane = tid & 31, warp = tid >> 5;
    if (tid < OUTD) fu[tid] = g_Fu[row * OUTD + tid];
    for (int i = tid; i < 256; i += 128) hist[i] = 0;
    __syncthreads();
    int cnt = g_cnt[row];
    for (int s = warp; s < MAXDEG; s += 4) {
        float yv;
        if (s < cnt) {
            int j = g_cols[row * MAXDEG + s];
            float p = fu[lane] * g_Fu[j * OUTD + lane]
                    + fu[lane + 32] * g_Fu[j * OUTD + lane + 32];
#pragma unroll
            for (int o = 16; o; o >>= 1) p += __shfl_xor_sync(0xffffffffu, p, o);
            yv = fminf(fmaxf(1.0f - p, 0.0f), 2.0f);
        } else {
            yv = __int_as_float(0x7f800000);   // +inf padding: sorts past all real y
        }
        if (lane == 0) {
            g_y[row * MAXDEG + s] = yv;
            atomicAdd(&hist[__float_as_uint(yv) >> 24], 1u);
        }
    }
    __syncthreads();
    for (int i = tid; i < 256; i += 128)
        if (hist[i]) atomicAdd(&g_hist0[i], hist[i]);
}

// ---------------- radix-select init: consume hist0 (bits 31:24) -------------
__global__ void init_select_kernel() {
    if (threadIdx.x == 0) {
        int M = g_M;
        double idx = 0.75 * (double)(M - 1);
        long   k0  = (long)floor(idx);
        g_frac = (float)(idx - (double)k0);
        int R[2];
        R[0] = (int)k0;
        long k1 = k0 + 1; if (k1 > (long)(M - 1)) k1 = M - 1;
        R[1] = (int)k1;
        for (int t = 0; t < 2; t++) {
            int r = R[t]; unsigned cum = 0; int b = 255;
            for (int bb = 0; bb < 256; bb++) {
                unsigned c = g_hist0[bb];
                if (cum + c > (unsigned)r) { b = bb; break; }
                cum += c;
            }
            g_prefix[t] = (unsigned)b << 24;
            g_rank[t]   = r - (int)cum;
        }
    }
    for (int i = threadIdx.x; i < 512; i += blockDim.x) g_hist[i] = 0;
}

// ---------------- radix-select round (bits SHIFT+7 : SHIFT) -----------------
template <int SHIFT>
__global__ __launch_bounds__(256) void sel_kernel(const float* __restrict__ lg0,
                                                  const float* __restrict__ rdec,
                                                  const float* __restrict__ ralpha,
                                                  int kiter) {
    __shared__ unsigned h[512];
    int tid = threadIdx.x;
    for (int i = tid; i < 512; i += 256) h[i] = 0;
    __syncthreads();
    const unsigned hm = (SHIFT == 16) ? 0xFF000000u
                       : (SHIFT == 8) ? 0xFFFF0000u : 0xFFFFFF00u;
    unsigned p0 = g_prefix[0], p1 = g_prefix[1];
    const int T = N_NODES * MAXDEG;
    for (int s = blockIdx.x * 256 + tid; s < T; s += gridDim.x * 256) {
        unsigned u = __float_as_uint(g_y[s]);
        unsigned b = (u >> SHIFT) & 0xFFu;
        if ((u & hm) == p0) atomicAdd(&h[b], 1u);
        if ((u & hm) == p1) atomicAdd(&h[256 + b], 1u);
    }
    __syncthreads();
    for (int i = tid; i < 512; i += 256)
        if (h[i]) atomicAdd(&g_hist[i], h[i]);
    __threadfence();
    __shared__ int slast;
    if (tid == 0) slast = (atomicAdd(&g_ticket, 1) == (int)gridDim.x - 1);
    __syncthreads();
    if (!slast) return;
    if (tid == 0) {
        for (int t = 0; t < 2; t++) {
            int r = g_rank[t]; unsigned cum = 0; int b = 255;
            for (int bb = 0; bb < 256; bb++) {
                unsigned c = g_hist[t * 256 + bb];
                if (cum + c > (unsigned)r) { b = bb; break; }
                cum += c;
            }
            g_prefix[t] |= (unsigned)b << SHIFT;
            g_rank[t]    = r - (int)cum;
        }
        g_ticket = 0;
        if (SHIFT == 0) {
            float v0 = __uint_as_float(g_prefix[0]);
            float v1 = __uint_as_float(g_prefix[1]);
            float fr = g_frac;
            float gd = v0 * (1.0f - fr) + v1 * fr;     // linear interpolation
            gd = fmaxf(gd, EPSV);
            float g0 = expf(lg0[0]);
            float rr = 1.0f / (1.0f + expf(-rdec[0]));
            float gp = g0 * powf(rr, (float)kiter);
            float al = 1.0f / (1.0f + expf(-ralpha[0]));
            g_lamc = al * (gp / A_SCAD) + (1.0f - al) * (gd / A_SCAD);
        }
    }
    __syncthreads();                 // scan done before zeroing the hist
    for (int i = tid; i < 512; i += 256) g_hist[i] = 0;
}

// ------- SCAD weights + sparse propagation (+fused normalize, hist0 zeroing) --
__global__ __launch_bounds__(64) void propagate_kernel(const float* __restrict__ Fin,
                                                       float* __restrict__ Fout,
                                                       float lam, int write_fu) {
    __shared__ float ssc[MAXDEG];
    __shared__ int   sj[MAXDEG];
    __shared__ float red[2];
    int row = blockIdx.x, t = threadIdx.x;

    // zero hist0 for the next iteration's ycompute (rows 0..3 cover 256 bins)
    {
        int gid = row * 64 + t;
        if (gid < 256) g_hist0[gid] = 0;
    }

    int cnt = g_cnt[row];
    float lamc = g_lamc;
    float di = g_dsq[row];
    float ps = 0.0f;
    for (int e = t; e < cnt; e += 64) {
        float y  = g_y[row * MAXDEG + e];
        float ys = fmaxf(y, EPSV);
        float wm = (A_SCAD * lamc - y) / ((A_SCAD - 1.0f) * ys);
        float w  = (y <= lamc) ? 1.0f : ((y <= A_SCAD * lamc) ? wm : 0.0f);
        int j = g_cols[row * MAXDEG + e];
        ssc[e] = w / (di * g_dsq[j]);        // W * A_tilde at the edge
        sj[e]  = j;
        ps += w;
    }
    // block reduce of ps (2 warps)
#pragma unroll
    for (int o = 16; o; o >>= 1) ps += __shfl_xor_sync(0xffffffffu, ps, o);
    if ((t & 31) == 0) red[t >> 5] = ps;
    __syncthreads();
    float S = red[0] + red[1];
    float Q = S / (float)(cnt + 1) + lam;    // D = cnt + 1 (self-loop)
    float acc = 0.0f;
    for (int e = 0; e < cnt; e++)
        acc = fmaf(ssc[e], Fin[sj[e] * OUTD + t], acc);
    float f0 = g_F0[row * OUTD + t];
    float outv = acc / Q + lam * f0 / Q;
    Fout[row * OUTD + t] = outv;

    if (write_fu) {                          // fused normalize for the NEXT iter
        float v = outv / di;
        float s2 = v * v;
#pragma unroll
        for (int o = 16; o; o >>= 1) s2 += __shfl_xor_sync(0xffffffffu, s2, o);
        __shared__ float red2[2];
        if ((t & 31) == 0) red2[t >> 5] = s2;
        __syncthreads();
        float nrm = sqrtf(red2[0] + red2[1]);
        g_Fu[row * OUTD + t] = v / fmaxf(nrm, EPSV);
    }
}

// ---------------- host launcher ---------------------------------------------
extern "C" void kernel_launch(void* const* d_in, const int* in_sizes, int n_in,
                              void* d_out, int out_size) {
    const float* A      = (const float*)d_in[0];
    const float* X      = (const float*)d_in[1];
    const float* W1     = (const float*)d_in[2];
    const float* b1     = (const float*)d_in[3];
    const float* W2     = (const float*)d_in[4];
    const float* b2     = (const float*)d_in[5];
    const float* lg0    = (const float*)d_in[6];
    const float* rdec   = (const float*)d_in[7];
    const float* ralpha = (const float*)d_in[8];
    float* out = (float*)d_out;

    float *pH, *pF0, *pFA, *pFB;
    cudaGetSymbolAddress((void**)&pH,  g_H);
    cudaGetSymbolAddress((void**)&pF0, g_F0);
    cudaGetSymbolAddress((void**)&pFA, g_FA);
    cudaGetSymbolAddress((void**)&pFB, g_FB);

    reset_kernel<<<1, 512>>>();
    build_kernel<<<N_NODES, 256>>>(A);

    // F0 = relu(X @ W1 + b1) @ W2 + b2
    gemm64<true ><<<dim3(H_DIM / 64, N_NODES / 64), 256>>>(X, W1, b1, pH,
                                                           N_NODES, H_DIM, IN_DIM);
    gemm64<false><<<dim3(OUTD / 64, N_NODES / 64), 256>>>(pH, W2, b2, pF0,
                                                          N_NODES, OUTD, H_DIM);
    normalize0_kernel<<<(N_NODES * 32 + 255) / 256, 256>>>(pF0);

    const int SELB = 256;
    for (int k = 0; k < PROP_STEP; k++) {
        const float* Fin = (k == 0) ? pF0 : ((k & 1) ? pFA : pFB);
        float* Fout = (k == PROP_STEP - 1) ? out : ((k & 1) ? pFB : pFA);

        ycompute_kernel<<<N_NODES, 128>>>();
        init_select_kernel<<<1, 256>>>();
        sel_kernel<16><<<SELB, 256>>>(lg0, rdec, ralpha, k);
        sel_kernel< 8><<<SELB, 256>>>(lg0, rdec, ralpha, k);
        sel_kernel< 0><<<SELB, 256>>>(lg0, rdec, ralpha, k);
        propagate_kernel<<<N_NODES, 64>>>(Fin, Fout, LAMF, (k < PROP_STEP - 1) ? 1 : 0);
    }
}

// round 5
// speedup vs baseline: 2.2889x; 1.6932x over previous
#include <cuda_runtime.h>
#include <math.h>

// Problem constants (fixed by setup_inputs)
#define N_NODES 4096
#define IN_DIM  512
#define H_DIM   256
#define OUTD    64
#define MAXDEG  192
#define EPSV    1e-8f
#define A_SCAD  3.7f
#define PROP_STEP 4
#define SEL_BLOCKS 148        // <= SM count: all blocks co-resident -> spin barrier is safe

static const float LAMF = (float)(1.0 / 0.9 - 1.0);   // 1/LAM_HAT - 1

// ---------------- device scratch (static, no allocation) ----------------
__device__ float g_dsq[N_NODES];
__device__ int   g_cnt[N_NODES];
__device__ int   g_cols[N_NODES * MAXDEG];
__device__ float g_y   [N_NODES * MAXDEG];
__device__ float g_Fu  [N_NODES * OUTD];
__device__ float g_F0  [N_NODES * OUTD];
__device__ float g_FA  [N_NODES * OUTD];
__device__ float g_FB  [N_NODES * OUTD];
__device__ float g_H   [N_NODES * H_DIM];
__device__ unsigned g_hist0[256];
__device__ unsigned g_selh[3][512];    // per-pass buffers (no inter-pass zeroing races)
__device__ float    g_lamc;
__device__ int      g_M;
__device__ int          g_bar_count;
__device__ volatile int g_bar_phase;

// ---------------- grid barrier (requires all blocks co-resident) ------------
__device__ __forceinline__ void grid_bar(int nb) {
    __syncthreads();
    if (threadIdx.x == 0) {
        __threadfence();
        int gen = g_bar_phase;
        if (atomicAdd(&g_bar_count, 1) == nb - 1) {
            g_bar_count = 0;
            __threadfence();
            g_bar_phase = gen + 1;
        } else {
            while (g_bar_phase == gen) __nanosleep(64);
        }
        __threadfence();
    }
    __syncthreads();
}

// ---------------- reset ----------------
__global__ void reset_kernel() {
    int i = threadIdx.x;
    if (i == 0) { g_M = 0; g_bar_count = 0; g_bar_phase = 0; }
    if (i < 256) g_hist0[i] = 0;
    for (int j = i; j < 3 * 512; j += blockDim.x) ((unsigned*)g_selh)[j] = 0;
}

// ---------------- build padded adjacency (deterministic, column-sorted) ----
__global__ __launch_bounds__(256) void build_kernel(const float* __restrict__ A) {
    __shared__ unsigned char sbit[N_NODES];
    __shared__ int scnt[256];
    int row = blockIdx.x, tid = threadIdx.x;
    const float* Arow = A + (size_t)row * N_NODES;
    for (int i = tid; i < N_NODES; i += 256) sbit[i] = (Arow[i] != 0.0f);
    __syncthreads();
    int c0 = tid * 16;
    int cnt = 0;
#pragma unroll
    for (int c = 0; c < 16; c++) cnt += sbit[c0 + c];
    scnt[tid] = cnt;
    __syncthreads();
    for (int off = 1; off < 256; off <<= 1) {
        int v = (tid >= off) ? scnt[tid - off] : 0;
        __syncthreads();
        scnt[tid] += v;
        __syncthreads();
    }
    int base  = scnt[tid] - cnt;
    int total = scnt[255];
    int pos = base;
    for (int c = 0; c < 16; c++)
        if (sbit[c0 + c] && pos < MAXDEG) g_cols[row * MAXDEG + (pos++)] = c0 + c;
    int t = min(total, MAXDEG);
    // one-time +inf padding of g_y (never rewritten; sorts past all real y)
    for (int e = t + tid; e < MAXDEG; e += 256)
        g_y[row * MAXDEG + e] = __int_as_float(0x7f800000);
    if (tid == 0) {
        g_cnt[row] = t;
        g_dsq[row] = sqrtf((float)(total + 1));   // D = deg + self-loop
        atomicAdd(&g_M, t);
    }
}

// ---------------- software-pipelined fp32 GEMM1: H = relu(X @ W1 + b1) ------
__global__ __launch_bounds__(256) void gemm1_kernel(const float* __restrict__ A,
                                                    const float* __restrict__ B,
                                                    const float* __restrict__ bias,
                                                    float* __restrict__ C) {
    const int N = H_DIM, K = IN_DIM;
    __shared__ float As[16][64];
    __shared__ float Bs[16][64];
    int tid = threadIdx.x;
    int tx = tid & 15, ty = tid >> 4;
    int row0 = blockIdx.y * 64, col0 = blockIdx.x * 64;
    int ar = tid >> 2, ak = (tid & 3) * 4;
    int bk = tid >> 4, bc = (tid & 15) * 4;
    const float* Aptr = A + (size_t)(row0 + ar) * K + ak;
    const float* Bptr = B + (size_t)bk * N + col0 + bc;

    float acc[4][4];
#pragma unroll
    for (int i = 0; i < 4; i++)
#pragma unroll
        for (int j = 0; j < 4; j++) acc[i][j] = 0.0f;

    float4 av = *(const float4*)Aptr;
    float4 bv = *(const float4*)Bptr;

    for (int k0 = 0; k0 < K; k0 += 16) {
        As[ak + 0][ar] = av.x; As[ak + 1][ar] = av.y;
        As[ak + 2][ar] = av.z; As[ak + 3][ar] = av.w;
        *(float4*)&Bs[bk][bc] = bv;
        __syncthreads();
        if (k0 + 16 < K) {
            av = *(const float4*)(Aptr + k0 + 16);
            bv = *(const float4*)(Bptr + (size_t)(k0 + 16) * N);
        }
#pragma unroll
        for (int kk = 0; kk < 16; kk++) {
            float4 a = *(float4*)&As[kk][ty * 4];
            float4 b = *(float4*)&Bs[kk][tx * 4];
            float avr[4] = {a.x, a.y, a.z, a.w};
            float bvr[4] = {b.x, b.y, b.z, b.w};
#pragma unroll
            for (int i = 0; i < 4; i++)
#pragma unroll
                for (int j = 0; j < 4; j++) acc[i][j] = fmaf(avr[i], bvr[j], acc[i][j]);
        }
        __syncthreads();
    }
#pragma unroll
    for (int i = 0; i < 4; i++) {
        int r = row0 + ty * 4 + i;
        float4 o;
        o.x = fmaxf(acc[i][0] + bias[col0 + tx * 4 + 0], 0.0f);
        o.y = fmaxf(acc[i][1] + bias[col0 + tx * 4 + 1], 0.0f);
        o.z = fmaxf(acc[i][2] + bias[col0 + tx * 4 + 2], 0.0f);
        o.w = fmaxf(acc[i][3] + bias[col0 + tx * 4 + 3], 0.0f);
        *(float4*)&C[(size_t)r * N + col0 + tx * 4] = o;
    }
}

// ------ GEMM2 fused: F0 = H @ W2 + b2 ; Fu = rownorm(F0 / dsq) --------------
// N = OUTD = 64 -> grid.x = 1: every block owns complete rows.
__global__ __launch_bounds__(256) void gemm2_fused_kernel(const float* __restrict__ A,
                                                          const float* __restrict__ B,
                                                          const float* __restrict__ bias) {
    const int N = OUTD, K = H_DIM;
    __shared__ float As[16][64];
    __shared__ float Bs[16][64];
    int tid = threadIdx.x;
    int tx = tid & 15, ty = tid >> 4;
    int row0 = blockIdx.y * 64;
    int ar = tid >> 2, ak = (tid & 3) * 4;
    int bk = tid >> 4, bc = (tid & 15) * 4;
    const float* Aptr = A + (size_t)(row0 + ar) * K + ak;
    const float* Bptr = B + (size_t)bk * N + bc;

    float acc[4][4];
#pragma unroll
    for (int i = 0; i < 4; i++)
#pragma unroll
        for (int j = 0; j < 4; j++) acc[i][j] = 0.0f;

    float4 av = *(const float4*)Aptr;
    float4 bv = *(const float4*)Bptr;

    for (int k0 = 0; k0 < K; k0 += 16) {
        As[ak + 0][ar] = av.x; As[ak + 1][ar] = av.y;
        As[ak + 2][ar] = av.z; As[ak + 3][ar] = av.w;
        *(float4*)&Bs[bk][bc] = bv;
        __syncthreads();
        if (k0 + 16 < K) {
            av = *(const float4*)(Aptr + k0 + 16);
            bv = *(const float4*)(Bptr + (size_t)(k0 + 16) * N);
        }
#pragma unroll
        for (int kk = 0; kk < 16; kk++) {
            float4 a = *(float4*)&As[kk][ty * 4];
            float4 b = *(float4*)&Bs[kk][tx * 4];
            float avr[4] = {a.x, a.y, a.z, a.w};
            float bvr[4] = {b.x, b.y, b.z, b.w};
#pragma unroll
            for (int i = 0; i < 4; i++)
#pragma unroll
                for (int j = 0; j < 4; j++) acc[i][j] = fmaf(avr[i], bvr[j], acc[i][j]);
        }
        __syncthreads();
    }
    // epilogue: F0 store + fused normalize -> Fu  (row spread over 16 lanes)
#pragma unroll
    for (int i = 0; i < 4; i++) {
        int r = row0 + ty * 4 + i;
        float4 o;
        o.x = acc[i][0] + bias[tx * 4 + 0];
        o.y = acc[i][1] + bias[tx * 4 + 1];
        o.z = acc[i][2] + bias[tx * 4 + 2];
        o.w = acc[i][3] + bias[tx * 4 + 3];
        *(float4*)&g_F0[r * OUTD + tx * 4] = o;
        float d = g_dsq[r];
        float vx = o.x / d, vy = o.y / d, vz = o.z / d, vw = o.w / d;
        float p = vx * vx + vy * vy + vz * vz + vw * vw;
#pragma unroll
        for (int off = 8; off; off >>= 1) p += __shfl_xor_sync(0xffffffffu, p, off);
        float inv = 1.0f / fmaxf(sqrtf(p), EPSV);
        float4 fo;
        fo.x = vx * inv; fo.y = vy * inv; fo.z = vz * inv; fo.w = vw * inv;
        *(float4*)&g_Fu[r * OUTD + tx * 4] = fo;
    }
}

// -------- per-edge y = clip(1 - Fu_i.Fu_j), 8 warps, 2-way ILP --------------
__global__ __launch_bounds__(256) void ycompute_kernel() {
    __shared__ float fu[OUTD];
    __shared__ unsigned hist[256];
    int row = blockIdx.x, tid = threadIdx.x;
    int lane = tid & 31, warp = tid >> 5;
    if (tid < OUTD) fu[tid] = g_Fu[row * OUTD + tid];
    hist[tid] = 0;
    __syncthreads();
    int cnt = g_cnt[row];
    const int* cols = g_cols + row * MAXDEG;
    float* yrow = g_y + row * MAXDEG;
    for (int e1 = warp; e1 < cnt; e1 += 16) {
        int e2 = e1 + 8;
        bool h2 = e2 < cnt;
        int j1 = cols[e1] * OUTD;
        int j2 = (h2 ? cols[e2] : cols[e1]) * OUTD;
        float p1 = fu[lane] * g_Fu[j1 + lane] + fu[lane + 32] * g_Fu[j1 + lane + 32];
        float p2 = fu[lane] * g_Fu[j2 + lane] + fu[lane + 32] * g_Fu[j2 + lane + 32];
#pragma unroll
        for (int o = 16; o; o >>= 1) {
            p1 += __shfl_xor_sync(0xffffffffu, p1, o);
            p2 += __shfl_xor_sync(0xffffffffu, p2, o);
        }
        if (lane == 0) {
            float y1 = fminf(fmaxf(1.0f - p1, 0.0f), 2.0f);
            yrow[e1] = y1;
            atomicAdd(&hist[__float_as_uint(y1) >> 24], 1u);
            if (h2) {
                float y2 = fminf(fmaxf(1.0f - p2, 0.0f), 2.0f);
                yrow[e2] = y2;
                atomicAdd(&hist[__float_as_uint(y2) >> 24], 1u);
            }
        }
    }
    __syncthreads();
    if (hist[tid]) atomicAdd(&g_hist0[tid], hist[tid]);
}

// -------- fused exact radix select: init + 3 passes, grid-sync'd ------------
__global__ __launch_bounds__(256) void sel_fused_kernel(const float* __restrict__ lg0,
                                                        const float* __restrict__ rdec,
                                                        const float* __restrict__ ralpha,
                                                        int kiter) {
    __shared__ unsigned h[512];
    __shared__ unsigned sscan[256];
    __shared__ unsigned sprefix[2];
    __shared__ int      srank[2];
    int tid = threadIdx.x;
    int M = g_M;

    float g0 = expf(lg0[0]);
    float rr = 1.0f / (1.0f + expf(-rdec[0]));
    float gp = g0 * powf(rr, (float)kiter);
    float al = 1.0f / (1.0f + expf(-ralpha[0]));

    if (M <= 0) {       // uniform across all blocks: no barrier imbalance
        if (blockIdx.x == 0 && tid == 0) {
            float gd = 1.0f;
            g_lamc = al * (gp / A_SCAD) + (1.0f - al) * (gd / A_SCAD);
        }
        return;
    }

    double idx = 0.75 * (double)(M - 1);
    long k0l = (long)floor(idx);
    float frac = (float)(idx - (double)k0l);
    int R0 = (int)k0l;
    long k1l = k0l + 1; if (k1l > (long)(M - 1)) k1l = M - 1;
    int R1 = (int)k1l;

    // level-0: scan g_hist0, locate top-byte bins for both ranks (per-block, redundant)
    unsigned c = g_hist0[tid];
    sscan[tid] = c;
    __syncthreads();
    for (int off = 1; off < 256; off <<= 1) {
        unsigned v = (tid >= off) ? sscan[tid - off] : 0;
        __syncthreads();
        sscan[tid] += v;
        __syncthreads();
    }
    {
        unsigned incl = sscan[tid], excl = incl - c;
        if ((unsigned)R0 >= excl && (unsigned)R0 < incl) { sprefix[0] = (unsigned)tid << 24; srank[0] = R0 - (int)excl; }
        if ((unsigned)R1 >= excl && (unsigned)R1 < incl) { sprefix[1] = (unsigned)tid << 24; srank[1] = R1 - (int)excl; }
    }
    __syncthreads();
    unsigned p0 = sprefix[0], p1 = sprefix[1];
    int r0 = srank[0], r1 = srank[1];
    __syncthreads();

    const int SH[3] = {16, 8, 0};
    for (int p = 0; p < 3; p++) {
        int sh = SH[p];
        unsigned hm = (sh == 16) ? 0xFF000000u : (sh == 8) ? 0xFFFF0000u : 0xFFFFFF00u;
        h[tid] = 0; h[tid + 256] = 0;
        __syncthreads();
        const int T = N_NODES * MAXDEG;
        for (int s = blockIdx.x * 256 + tid; s < T; s += SEL_BLOCKS * 256) {
            unsigned u = __float_as_uint(g_y[s]);
            unsigned b = (u >> sh) & 0xFFu;
            if ((u & hm) == p0) atomicAdd(&h[b], 1u);
            if ((u & hm) == p1) atomicAdd(&h[256 + b], 1u);
        }
        __syncthreads();
        if (h[tid])       atomicAdd(&g_selh[p][tid], h[tid]);
        if (h[tid + 256]) atomicAdd(&g_selh[p][tid + 256], h[tid + 256]);
        grid_bar(SEL_BLOCKS);
        // each block redundantly scans the completed pass histogram
        for (int t = 0; t < 2; t++) {
            unsigned cc = g_selh[p][t * 256 + tid];
            sscan[tid] = cc;
            __syncthreads();
            for (int off = 1; off < 256; off <<= 1) {
                unsigned v = (tid >= off) ? sscan[tid - off] : 0;
                __syncthreads();
                sscan[tid] += v;
                __syncthreads();
            }
            unsigned incl = sscan[tid], excl = incl - cc;
            int r = (t == 0) ? r0 : r1;
            if ((unsigned)r >= excl && (unsigned)r < incl) {
                sprefix[t] = ((t == 0) ? p0 : p1) | ((unsigned)tid << sh);
                srank[t] = r - (int)excl;
            }
            __syncthreads();
        }
        p0 = sprefix[0]; p1 = sprefix[1];
        r0 = srank[0];   r1 = srank[1];
        __syncthreads();
    }
    if (blockIdx.x == 0 && tid == 0) {
        float v0 = __uint_as_float(p0);
        float v1 = __uint_as_float(p1);
        float gd = fmaxf(v0 * (1.0f - frac) + v1 * frac, EPSV);
        g_lamc = al * (gp / A_SCAD) + (1.0f - al) * (gd / A_SCAD);
    }
}

// ------- SCAD weights + sparse propagation (+fused normalize, hist zeroing) --
__global__ __launch_bounds__(64) void propagate_kernel(const float* __restrict__ Fin,
                                                       float* __restrict__ Fout,
                                                       float lam, int write_fu) {
    __shared__ float ssc[MAXDEG];
    __shared__ int   sj[MAXDEG];
    __shared__ float red[2];
    int row = blockIdx.x, t = threadIdx.x;

    // zero histograms for next iteration (rows 0..27 cover 256 + 1536 words)
    {
        int gid = row * 64 + t;
        if (gid < 256) g_hist0[gid] = 0;
        else if (gid < 256 + 3 * 512) ((unsigned*)g_selh)[gid - 256] = 0;
    }

    int cnt = g_cnt[row];
    float lamc = g_lamc;
    float di = g_dsq[row];
    float ps = 0.0f;
    for (int e = t; e < cnt; e += 64) {
        float y  = g_y[row * MAXDEG + e];
        float ys = fmaxf(y, EPSV);
        float wm = (A_SCAD * lamc - y) / ((A_SCAD - 1.0f) * ys);
        float w  = (y <= lamc) ? 1.0f : ((y <= A_SCAD * lamc) ? wm : 0.0f);
        int j = g_cols[row * MAXDEG + e];
        ssc[e] = w / (di * g_dsq[j]);
        sj[e]  = j;
        ps += w;
    }
#pragma unroll
    for (int o = 16; o; o >>= 1) ps += __shfl_xor_sync(0xffffffffu, ps, o);
    if ((t & 31) == 0) red[t >> 5] = ps;
    __syncthreads();
    float S = red[0] + red[1];
    float Q = S / (float)(cnt + 1) + lam;
    // 4-accumulator gather (MLP)
    float a0 = 0.0f, a1 = 0.0f, a2 = 0.0f, a3 = 0.0f;
    int e = 0;
    for (; e + 4 <= cnt; e += 4) {
        a0 = fmaf(ssc[e + 0], Fin[sj[e + 0] * OUTD + t], a0);
        a1 = fmaf(ssc[e + 1], Fin[sj[e + 1] * OUTD + t], a1);
        a2 = fmaf(ssc[e + 2], Fin[sj[e + 2] * OUTD + t], a2);
        a3 = fmaf(ssc[e + 3], Fin[sj[e + 3] * OUTD + t], a3);
    }
    for (; e < cnt; e++) a0 = fmaf(ssc[e], Fin[sj[e] * OUTD + t], a0);
    float acc = (a0 + a1) + (a2 + a3);
    float f0 = g_F0[row * OUTD + t];
    float outv = acc / Q + lam * f0 / Q;
    Fout[row * OUTD + t] = outv;

    if (write_fu) {
        float v = outv / di;
        float s2 = v * v;
#pragma unroll
        for (int o = 16; o; o >>= 1) s2 += __shfl_xor_sync(0xffffffffu, s2, o);
        __shared__ float red2[2];
        if ((t & 31) == 0) red2[t >> 5] = s2;
        __syncthreads();
        float nrm = sqrtf(red2[0] + red2[1]);
        g_Fu[row * OUTD + t] = v / fmaxf(nrm, EPSV);
    }
}

// ---------------- host launcher ---------------------------------------------
extern "C" void kernel_launch(void* const* d_in, const int* in_sizes, int n_in,
                              void* d_out, int out_size) {
    const float* A      = (const float*)d_in[0];
    const float* X      = (const float*)d_in[1];
    const float* W1     = (const float*)d_in[2];
    const float* b1     = (const float*)d_in[3];
    const float* W2     = (const float*)d_in[4];
    const float* b2     = (const float*)d_in[5];
    const float* lg0    = (const float*)d_in[6];
    const float* rdec   = (const float*)d_in[7];
    const float* ralpha = (const float*)d_in[8];
    float* out = (float*)d_out;

    float *pH, *pF0, *pFA, *pFB;
    cudaGetSymbolAddress((void**)&pH,  g_H);
    cudaGetSymbolAddress((void**)&pF0, g_F0);
    cudaGetSymbolAddress((void**)&pFA, g_FA);
    cudaGetSymbolAddress((void**)&pFB, g_FB);

    reset_kernel<<<1, 1024>>>();
    build_kernel<<<N_NODES, 256>>>(A);

    gemm1_kernel<<<dim3(H_DIM / 64, N_NODES / 64), 256>>>(X, W1, b1, pH);
    gemm2_fused_kernel<<<dim3(1, N_NODES / 64), 256>>>(pH, W2, b2);

    for (int k = 0; k < PROP_STEP; k++) {
        const float* Fin = (k == 0) ? pF0 : ((k & 1) ? pFA : pFB);
        float* Fout = (k == PROP_STEP - 1) ? out : ((k & 1) ? pFB : pFA);

        ycompute_kernel<<<N_NODES, 256>>>();
        sel_fused_kernel<<<SEL_BLOCKS, 256>>>(lg0, rdec, ralpha, k);
        propagate_kernel<<<N_NODES, 64>>>(Fin, Fout, LAMF, (k < PROP_STEP - 1) ? 1 : 0);
    }
}